// round 2
// baseline (speedup 1.0000x reference)
#include <cuda_runtime.h>
#include <cstdint>

// Problem shape (fixed by setup_inputs)
constexpr int Hh     = 512;
constexpr int Ww     = 512;
constexpr int PLANES = 64;            // B*C = 16*4
constexpr int NPIX   = Hh * Ww;       // 262144 per plane
constexpr int NVEC   = NPIX / 4;      // 65536 float4 per plane
constexpr int TPB    = 256;
constexpr int BPP    = 32;            // blocks per plane
constexpr int VPB    = NVEC / BPP;    // 2048 vec4 per block (16 rows)
constexpr int VPT    = VPB / TPB;     // 8 vec4 per thread

// Scratch accumulators (no device allocation allowed -> __device__ globals)
__device__ double g_ce;
__device__ double g_ed;
__device__ double g_inter[PLANES];
__device__ double g_isum[PLANES];
__device__ double g_jsum[PLANES];

__device__ __forceinline__ float ex2f(float x) { float y; asm("ex2.approx.f32 %0, %1;" : "=f"(y) : "f"(x)); return y; }
__device__ __forceinline__ float lg2f(float x) { float y; asm("lg2.approx.f32 %0, %1;" : "=f"(y) : "f"(x)); return y; }
__device__ __forceinline__ float rcpf(float x) { float y; asm("rcp.approx.f32 %0, %1;" : "=f"(y) : "f"(x)); return y; }

__global__ void zero_k() {
    int t = threadIdx.x;
    if (t < PLANES) { g_inter[t] = 0.0; g_isum[t] = 0.0; g_jsum[t] = 0.0; }
    else if (t == PLANES) { g_ce = 0.0; g_ed = 0.0; }
}

__global__ __launch_bounds__(TPB) void main_k(const float* __restrict__ cmap,
                                              const int*   __restrict__ gt) {
    const int plane = blockIdx.y;
    const float4* __restrict__ cp  = reinterpret_cast<const float4*>(cmap) + (size_t)plane * NVEC;
    const int4*   __restrict__ gp  = reinterpret_cast<const int4*>(gt)     + (size_t)plane * NVEC;
    const int*    __restrict__ gps = gt + (size_t)plane * NPIX;

    float ce = 0.f, ed = 0.f, inter = 0.f, jsum = 0.f;
    int   icnt = 0;

    const int vbase = blockIdx.x * VPB + threadIdx.x;
#pragma unroll
    for (int it = 0; it < VPT; ++it) {
        const int v  = vbase + it * TPB;
        const int w4 = v & (Ww / 4 - 1);       // 0..127
        const int h  = v >> 7;                 // 0..511

        const float4 x4 = __ldg(cp + v);
        const int4   c4 = __ldg(gp + v);
        int4 u4 = make_int4(0, 0, 0, 0);
        int4 d4 = make_int4(0, 0, 0, 0);
        if (h > 0)      u4 = __ldg(gp + v - Ww / 4);
        if (h < Hh - 1) d4 = __ldg(gp + v + Ww / 4);
        int lf = 0, rg = 0;
        if (w4 > 0)          lf = __ldg(gps + v * 4 - 1);
        if (w4 < Ww / 4 - 1) rg = __ldg(gps + v * 4 + 4);

        const int   cc[4] = {c4.x, c4.y, c4.z, c4.w};
        const int   uu[4] = {u4.x, u4.y, u4.z, u4.w};
        const int   dd[4] = {d4.x, d4.y, d4.z, d4.w};
        const float xx[4] = {x4.x, x4.y, x4.z, x4.w};

#pragma unroll
        for (int k = 0; k < 4; ++k) {
            const int l   = (k == 0) ? lf : cc[k - 1];
            const int r   = (k == 3) ? rg : cc[k + 1];
            const int orv = (cc[k] | uu[k]) | (dd[k] | l) | r;   // dilation (zero pad)
            const int anv = (cc[k] & uu[k]) & (dd[k] & l) & r;   // erosion  (zero pad)
            const int e   = orv & ~anv;                          // boundary bit {0,1}

            const float x  = xx[k];
            const float p  = ex2f(x * 1.4426950408889634f);      // e^x
            const float s  = 1.f + p;
            const float pr = p * rcpf(s);                        // sigmoid(x)
            const float sp = 0.6931471805599453f * lg2f(s);      // softplus(x)
            const float y  = (float)cc[k];

            ce += sp;
            ce  = fmaf(-x, y, ce);                               // ce += sp - x*y
            ed += e ? fminf(sp, 100.f) : 0.f;                    // edge term
            inter = fmaf(y, pr, inter);
            jsum += pr;
            icnt += cc[k];
        }
    }

    // ---- block reduction ----
    const unsigned full = 0xFFFFFFFFu;
#pragma unroll
    for (int off = 16; off > 0; off >>= 1) {
        ce    += __shfl_down_sync(full, ce, off);
        ed    += __shfl_down_sync(full, ed, off);
        inter += __shfl_down_sync(full, inter, off);
        jsum  += __shfl_down_sync(full, jsum, off);
        icnt  += __shfl_down_sync(full, icnt, off);
    }

    __shared__ float sm[4][TPB / 32];
    __shared__ int   smi[TPB / 32];
    const int wid = threadIdx.x >> 5;
    const int lid = threadIdx.x & 31;
    if (lid == 0) {
        sm[0][wid] = ce; sm[1][wid] = ed; sm[2][wid] = inter; sm[3][wid] = jsum;
        smi[wid] = icnt;
    }
    __syncthreads();
    if (threadIdx.x == 0) {
        float tce = 0.f, ted = 0.f, ti = 0.f, tj = 0.f;
        int   tc  = 0;
#pragma unroll
        for (int w = 0; w < TPB / 32; ++w) {
            tce += sm[0][w]; ted += sm[1][w]; ti += sm[2][w]; tj += sm[3][w];
            tc  += smi[w];
        }
        atomicAdd(&g_ce, (double)tce);
        atomicAdd(&g_ed, (double)ted);
        atomicAdd(&g_inter[plane], (double)ti);
        atomicAdd(&g_isum[plane],  (double)tc);
        atomicAdd(&g_jsum[plane],  (double)tj);
    }
}

__global__ void fin_k(float* __restrict__ out) {
    if (threadIdx.x == 0 && blockIdx.x == 0) {
        const double N = (double)PLANES * (double)NPIX;
        const double SMOOTH = 0.0001;
        double dice = 0.0;
#pragma unroll
        for (int p = 0; p < PLANES; ++p) {
            const double sc = (2.0 * g_inter[p] + SMOOTH) / (g_isum[p] + g_jsum[p] + SMOOTH);
            dice += (1.0 - sc);
        }
        dice *= (1.0 / 16.0);  // mean over batch (16), sum over classes
        out[0] = (float)(g_ce / N + g_ed / N + dice);
    }
}

extern "C" void kernel_launch(void* const* d_in, const int* in_sizes, int n_in,
                              void* d_out, int out_size) {
    const float* cmap = (const float*)d_in[0];
    const int*   gt   = (const int*)d_in[1];
    float*       out  = (float*)d_out;

    zero_k<<<1, 128>>>();
    dim3 grid(BPP, PLANES);
    main_k<<<grid, TPB>>>(cmap, gt);
    fin_k<<<1, 32>>>(out);
}

// round 4
// speedup vs baseline: 1.0032x; 1.0032x over previous
#include <cuda_runtime.h>
#include <cstdint>

// Problem shape (fixed by setup_inputs)
constexpr int Hh     = 512;
constexpr int Ww     = 512;
constexpr int PLANES = 64;             // B*C = 16*4
constexpr int NPIX   = Hh * Ww;        // 262144 per plane
constexpr int W4     = Ww / 4;         // 128 vec4 per row
constexpr int TPB    = 256;
constexpr int BANDS  = 32;             // 16 rows per band
constexpr int RPT    = 8;              // rows per thread
constexpr int TOTAL_BLOCKS = PLANES * BANDS;  // 2048

// Scratch accumulators (allocation-free: __device__ globals, zero-initialized)
__device__ double   g_ce;              // combined ce + edge numerator
__device__ double   g_inter[PLANES];
__device__ double   g_isum[PLANES];
__device__ double   g_jsum[PLANES];
__device__ unsigned g_count;

__device__ __forceinline__ float ex2f(float x) { float y; asm("ex2.approx.f32 %0, %1;" : "=f"(y) : "f"(x)); return y; }
__device__ __forceinline__ float lg2f(float x) { float y; asm("lg2.approx.f32 %0, %1;" : "=f"(y) : "f"(x)); return y; }
__device__ __forceinline__ float rcpf(float x) { float y; asm("rcp.approx.f32 %0, %1;" : "=f"(y) : "f"(x)); return y; }

// Pack four 0/1 int32 values into 4 bytes of one register (3 PRMT)
__device__ __forceinline__ unsigned pack01(int4 v) {
    unsigned t0 = __byte_perm((unsigned)v.x, (unsigned)v.y, 0x0040);
    unsigned t1 = __byte_perm((unsigned)v.z, (unsigned)v.w, 0x0040);
    return __byte_perm(t0, t1, 0x5410);   // [x0, y0, z0, w0]
}

__global__ __launch_bounds__(TPB) void fused_k(const float* __restrict__ cmap,
                                               const int*   __restrict__ gt,
                                               float*       __restrict__ out) {
    const int plane = blockIdx.y;
    const int band  = blockIdx.x;
    const int tid   = threadIdx.x;
    const int w4    = tid & (W4 - 1);            // vec4 column 0..127
    const int rgrp  = tid >> 7;                  // 0 or 1
    const int r0    = band * 16 + rgrp * RPT;    // first row of this thread
    const int lane  = tid & 31;

    const int4*   __restrict__ gp  = reinterpret_cast<const int4*>(gt)   + (size_t)plane * (NPIX / 4);
    const float4* __restrict__ cp  = reinterpret_cast<const float4*>(cmap) + (size_t)plane * (NPIX / 4);
    const int*    __restrict__ gts = gt + (size_t)plane * NPIX;

    const int4 zero4 = make_int4(0, 0, 0, 0);

    int4     cv  = __ldg(gp + r0 * W4 + w4);
    unsigned ppk = (r0 > 0) ? pack01(__ldg(gp + (r0 - 1) * W4 + w4)) : 0u;
    unsigned cpk = pack01(cv);

    float acc = 0.f, inter = 0.f, jsum = 0.f;
    int   icnt = 0;
    const unsigned FULL = 0xFFFFFFFFu;

#pragma unroll
    for (int i = 0; i < RPT; ++i) {
        const int h = r0 + i;
        int4 nv = zero4;
        if (h + 1 < Hh) nv = __ldg(gp + (h + 1) * W4 + w4);
        const float4 x4 = __ldg(cp + h * W4 + w4);
        const unsigned npk = pack01(nv);

        // horizontal neighbors: adjacent lanes own adjacent vec4 columns
        unsigned lsh = __shfl_up_sync(FULL, cpk, 1);
        unsigned rsh = __shfl_down_sync(FULL, cpk, 1);
        if (lane == 0)  { int lv = (w4 > 0)      ? __ldg(gts + h * Ww + w4 * 4 - 1) : 0; lsh = ((unsigned)lv) << 24; }
        if (lane == 31) { int rv = (w4 < W4 - 1) ? __ldg(gts + h * Ww + w4 * 4 + 4) : 0; rsh = (unsigned)rv; }
        const unsigned lpk = __funnelshift_l(lsh, cpk, 8);   // (cpk<<8) | (lsh>>24)
        const unsigned rpk = __funnelshift_r(cpk, rsh, 8);   // (cpk>>8) | (rsh<<24)

        // packed 5-point dilation / erosion / boundary, 4 px per op
        const unsigned orv = (cpk | ppk | npk) | lpk | rpk;
        const unsigned anv = (cpk & ppk & npk) & lpk & rpk;
        const unsigned e   = orv & ~anv;                     // each byte in {0,1}

        icnt += __popc(cpk);                                 // 0/1 values -> popcount = sum

        const float xx[4]  = {x4.x, x4.y, x4.z, x4.w};
        const int   ccv[4] = {cv.x, cv.y, cv.z, cv.w};
#pragma unroll
        for (int k = 0; k < 4; ++k) {
            const float x  = xx[k];
            const float p  = ex2f(x * 1.4426950408889634f);   // e^x
            const float s  = 1.f + p;
            const float pr = 1.f - rcpf(s);                   // sigmoid(x)
            const float sp = 0.6931471805599453f * lg2f(s);   // softplus(x)
            const float cf = (float)ccv[k];                   // y in {0,1}
            const float ef = (float)((e >> (8 * k)) & 1u);    // boundary in {0,1}

            acc += sp;                                        // ce numerator
            acc  = fmaf(-x, cf, acc);                         // ce: -x*y
            acc  = fmaf(fminf(sp, 100.f), ef, acc);           // edge term (same /N)
            inter = fmaf(pr, cf, inter);
            jsum += pr;
        }
        ppk = cpk; cpk = npk; cv = nv;
    }

    // ---- warp + block reduction ----
#pragma unroll
    for (int off = 16; off > 0; off >>= 1) {
        acc   += __shfl_down_sync(FULL, acc, off);
        inter += __shfl_down_sync(FULL, inter, off);
        jsum  += __shfl_down_sync(FULL, jsum, off);
        icnt  += __shfl_down_sync(FULL, icnt, off);
    }

    __shared__ float sA[TPB / 32], sI[TPB / 32], sJ[TPB / 32];
    __shared__ int   sC[TPB / 32];
    const int wid = tid >> 5;
    if (lane == 0) { sA[wid] = acc; sI[wid] = inter; sJ[wid] = jsum; sC[wid] = icnt; }
    __syncthreads();

    if (tid == 0) {
        float ta = 0.f, ti = 0.f, tj = 0.f;
        int   tc = 0;
#pragma unroll
        for (int w = 0; w < TPB / 32; ++w) { ta += sA[w]; ti += sI[w]; tj += sJ[w]; tc += sC[w]; }
        atomicAdd(&g_ce,           (double)ta);
        atomicAdd(&g_inter[plane], (double)ti);
        atomicAdd(&g_isum[plane],  (double)tc);
        atomicAdd(&g_jsum[plane],  (double)tj);

        __threadfence();
        const unsigned done = atomicAdd(&g_count, 1u);
        if (done == TOTAL_BLOCKS - 1) {
            __threadfence();
            volatile double* vi = g_inter;
            volatile double* vs = g_isum;
            volatile double* vj = g_jsum;
            volatile double* vc = &g_ce;

            const double N      = (double)PLANES * (double)NPIX;
            const double SMOOTH = 0.0001;
            double dice = 0.0;
#pragma unroll
            for (int p = 0; p < PLANES; ++p) {
                const double sc = (2.0 * vi[p] + SMOOTH) / (vs[p] + vj[p] + SMOOTH);
                dice += (1.0 - sc);
            }
            dice *= (1.0 / 16.0);                 // mean over batch, sum over classes
            out[0] = (float)(*vc / N + dice);

            // reset for the next graph replay (kernel starts from zeroed state)
#pragma unroll
            for (int p = 0; p < PLANES; ++p) { vi[p] = 0.0; vs[p] = 0.0; vj[p] = 0.0; }
            *vc = 0.0;
            g_count = 0u;
        }
    }
}

extern "C" void kernel_launch(void* const* d_in, const int* in_sizes, int n_in,
                              void* d_out, int out_size) {
    const float* cmap = (const float*)d_in[0];
    const int*   gt   = (const int*)d_in[1];
    float*       out  = (float*)d_out;

    dim3 grid(BANDS, PLANES);
    fused_k<<<grid, TPB>>>(cmap, gt, out);
}